// round 2
// baseline (speedup 1.0000x reference)
#include <cuda_runtime.h>
#include <math.h>

#define Bt    16
#define St    128
#define Nn    2048
#define Ee    2032
#define Hh    256
#define DINc  256
#define DEc   192
#define DRc   64
#define Lc    12
#define NLEVc 21
#define NCB   8
#define NGRP  18
#define NCTA  144

// ---------------- device scratch (no dynamic allocation allowed) ------------
__device__ float g_x [Nn * DINc];
__device__ float g_ix[Nn * Hh];
__device__ float g_fx[Nn * Hh];
__device__ float g_ox[Nn * Hh];
__device__ float g_ux[Nn * Hh];
__device__ float g_h [Nn * Hh];
__device__ float g_c [Nn * Hh];
__device__ int   g_child_start[Nn + 1];
__device__ int   g_child_list [Ee];
__device__ int   g_level_start[NLEVc + 1];
__device__ int   g_level_nodes[Nn];
__device__ unsigned g_bar_count;
__device__ unsigned g_bar_gen;

// ---------------- preprocess: child CSR + level lists (single block) --------
__global__ void __launch_bounds__(256) preprocess_kernel(
    const int* __restrict__ child_idx,
    const int* __restrict__ parent_idx,
    const int* __restrict__ node_height)
{
    __shared__ int s_cnt[Nn];         // counts -> start cursors
    __shared__ int s_aux[256];
    __shared__ int s_lvl[NLEVc + 1];
    const int t = threadIdx.x;

    for (int i = t; i < Nn; i += 256) s_cnt[i] = 0;
    if (t <= NLEVc) s_lvl[t] = 0;
    __syncthreads();

    for (int e = t; e < Ee; e += 256) atomicAdd(&s_cnt[parent_idx[e]], 1);
    for (int i = t; i < Nn; i += 256) atomicAdd(&s_lvl[node_height[i]], 1);
    __syncthreads();

    // exclusive scan of 2048 child counts: 8 per thread + 256-wide scan
    int v[8]; int s = 0;
#pragma unroll
    for (int r = 0; r < 8; r++) { v[r] = s_cnt[t * 8 + r]; s += v[r]; }
    s_aux[t] = s;
    __syncthreads();
    for (int off = 1; off < 256; off <<= 1) {
        int x = (t >= off) ? s_aux[t - off] : 0;
        __syncthreads();
        s_aux[t] += x;
        __syncthreads();
    }
    int run = (t == 0) ? 0 : s_aux[t - 1];
#pragma unroll
    for (int r = 0; r < 8; r++) {
        int c = v[r];
        g_child_start[t * 8 + r] = run;
        s_cnt[t * 8 + r] = run;         // becomes scatter cursor
        run += c;
    }
    if (t == 255) g_child_start[Nn] = run;
    __syncthreads();

    if (t == 0) {
        int acc = 0;
        for (int l = 0; l < NLEVc; l++) {
            int c = s_lvl[l];
            g_level_start[l] = acc;
            s_lvl[l] = acc;
            acc += c;
        }
        g_level_start[NLEVc] = acc;
    }
    __syncthreads();

    // deterministic child scatter: one thread per tree, edges in ascending
    // child order (parents are tree-local -> cursors disjoint across threads)
    if (t < Bt) {
        for (int e = t * (St - 1); e < (t + 1) * (St - 1); e++) {
            int p = parent_idx[e];
            g_child_list[s_cnt[p]++] = child_idx[e];
        }
    }
    // level-node scatter (intra-level order is numerically irrelevant)
    for (int i = t; i < Nn; i += 256) {
        int pos = atomicAdd(&s_lvl[node_height[i]], 1);
        g_level_nodes[pos] = i;
    }
}

// ---------------- embedding gather ------------------------------------------
__global__ void __launch_bounds__(256) embed_kernel(
    const int* __restrict__ xs, const int* __restrict__ rels,
    const float* __restrict__ embW, const float* __restrict__ relW)
{
    int i = blockIdx.x * blockDim.x + threadIdx.x;
    int idx = i * 4;
    if (idx >= Nn * DINc) return;
    int n = idx >> 8;
    int d = idx & 255;
    float4 vv;
    if (d < DEc) vv = *(const float4*)(embW + (size_t)xs[n] * DEc + d);
    else         vv = *(const float4*)(relW + (size_t)rels[n] * DRc + (d - DEc));
    *(float4*)(g_x + idx) = vv;
}

// ---------------- fused input GEMMs: g_x[2048,256] @ W[256,256] (x4) --------
__global__ void __launch_bounds__(256) input_gemm_kernel(
    const float* __restrict__ Wix, const float* __restrict__ Wfx,
    const float* __restrict__ Wox, const float* __restrict__ Wux,
    const float* __restrict__ bix, const float* __restrict__ bfx)
{
    __shared__ __align__(16) float As[16][68];
    __shared__ __align__(16) float Bs[16][68];
    const int mz = blockIdx.z;
    const float* W  = (mz == 0) ? Wix : (mz == 1) ? Wfx : (mz == 2) ? Wox : Wux;
    const float* bp = (mz == 0) ? bix : (mz == 1) ? bfx : nullptr;
    float* O = (mz == 0) ? g_ix : (mz == 1) ? g_fx : (mz == 2) ? g_ox : g_ux;

    const int t = threadIdx.x;
    const int tx = t & 15, ty = t >> 4;
    const int row0 = blockIdx.y * 64, col0 = blockIdx.x * 64;
    float acc[4][4] = {};

    for (int kk = 0; kk < 256; kk += 16) {
        {
            int m = t >> 2, kq = (t & 3) * 4;
            float4 a = *(const float4*)(g_x + (row0 + m) * 256 + kk + kq);
            As[kq + 0][m] = a.x; As[kq + 1][m] = a.y;
            As[kq + 2][m] = a.z; As[kq + 3][m] = a.w;
            int k = t >> 4, nq = (t & 15) * 4;
            float4 b = *(const float4*)(W + (kk + k) * 256 + col0 + nq);
            *(float4*)&Bs[k][nq] = b;
        }
        __syncthreads();
#pragma unroll
        for (int k = 0; k < 16; k++) {
            float4 a = *(const float4*)&As[k][ty * 4];
            float4 b = *(const float4*)&Bs[k][tx * 4];
            acc[0][0] = fmaf(a.x, b.x, acc[0][0]); acc[0][1] = fmaf(a.x, b.y, acc[0][1]);
            acc[0][2] = fmaf(a.x, b.z, acc[0][2]); acc[0][3] = fmaf(a.x, b.w, acc[0][3]);
            acc[1][0] = fmaf(a.y, b.x, acc[1][0]); acc[1][1] = fmaf(a.y, b.y, acc[1][1]);
            acc[1][2] = fmaf(a.y, b.z, acc[1][2]); acc[1][3] = fmaf(a.y, b.w, acc[1][3]);
            acc[2][0] = fmaf(a.z, b.x, acc[2][0]); acc[2][1] = fmaf(a.z, b.y, acc[2][1]);
            acc[2][2] = fmaf(a.z, b.z, acc[2][2]); acc[2][3] = fmaf(a.z, b.w, acc[2][3]);
            acc[3][0] = fmaf(a.w, b.x, acc[3][0]); acc[3][1] = fmaf(a.w, b.y, acc[3][1]);
            acc[3][2] = fmaf(a.w, b.z, acc[3][2]); acc[3][3] = fmaf(a.w, b.w, acc[3][3]);
        }
        __syncthreads();
    }
    int cc0 = col0 + tx * 4;
    float4 bb = make_float4(0.f, 0.f, 0.f, 0.f);
    if (bp) bb = *(const float4*)(bp + cc0);
#pragma unroll
    for (int i2 = 0; i2 < 4; i2++) {
        int r = row0 + ty * 4 + i2;
        float4 o;
        o.x = acc[i2][0] + bb.x; o.y = acc[i2][1] + bb.y;
        o.z = acc[i2][2] + bb.z; o.w = acc[i2][3] + bb.w;
        *(float4*)(O + r * 256 + cc0) = o;
    }
}

// ---------------- persistent level-synchronous recurrence -------------------
__device__ __forceinline__ float sigm(float x) { return 1.f / (1.f + __expf(-x)); }

__global__ void __launch_bounds__(256) rec_kernel(
    const float* __restrict__ Wih, const float* __restrict__ Woh,
    const float* __restrict__ Wuh, const float* __restrict__ Wfh,
    const float* __restrict__ bih_g, const float* __restrict__ bfh_g)
{
    extern __shared__ __align__(16) float sm[];
    float* Wi = sm;
    float* Wo = sm + 8192;
    float* Wu = sm + 16384;
    float* Wf = sm + 24576;
    float* hchAll = sm + 32768;            // 8 x 256
    float* hsAll  = sm + 32768 + 2048;     // 8 x 256

    const int t = threadIdx.x;
    const int lane = t & 31, w = t >> 5;
    const int cb = blockIdx.x / NGRP;      // column block 0..7
    const int g  = blockIdx.x % NGRP;      // node group 0..17
    const int col = cb * 32 + lane;

    // load W column slices once (resident for the whole kernel)
    for (int i = t; i < 8192; i += 256) {
        int k = i >> 5, j = i & 31;
        int gidx = k * 256 + cb * 32 + j;
        Wi[i] = Wih[gidx];
        Wo[i] = Woh[gidx];
        Wu[i] = Wuh[gidx];
        Wf[i] = Wfh[gidx];
    }
    const float bih = bih_g[col];
    const float bfh = bfh_g[col];
    float* hch = hchAll + w * 256;
    float* hs  = hsAll  + w * 256;
    __syncthreads();

    for (int lev = 0; lev < NLEVc; lev++) {
        int lbeg = g_level_start[lev], lend = g_level_start[lev + 1];
        int cnt = lend - lbeg;
        int mycnt = (cnt > g) ? ((cnt - g + NGRP - 1) / NGRP) : 0;
        int iters = (mycnt + 7) >> 3;
        for (int it = 0; it < iters; it++) {
            int li = it * 8 + w;
            if (li < mycnt) {
                int n = g_level_nodes[lbeg + g + li * NGRP];
                int cs0 = g_child_start[n], cs1 = g_child_start[n + 1];
                float fxn = g_fx[n * 256 + col];
                float rs[8];
#pragma unroll
                for (int q = 0; q < 8; q++) rs[q] = 0.f;
                float fc = 0.f, id = 0.f, od = 0.f, ud = 0.f;

                for (int e = cs0; e < cs1; e++) {
                    int ch = g_child_list[e];
                    const float* hrow = g_h + ch * 256;
#pragma unroll
                    for (int q = 0; q < 8; q++) {
                        float vv = __ldcg(hrow + q * 32 + lane);
                        hch[q * 32 + lane] = vv;
                        rs[q] += vv;
                    }
                    __syncwarp();
                    float fd = 0.f;
#pragma unroll 8
                    for (int k = 0; k < 256; k += 4) {
                        float4 h4 = *(const float4*)(hch + k);
                        fd = fmaf(h4.x, Wf[(k + 0) * 32 + lane], fd);
                        fd = fmaf(h4.y, Wf[(k + 1) * 32 + lane], fd);
                        fd = fmaf(h4.z, Wf[(k + 2) * 32 + lane], fd);
                        fd = fmaf(h4.w, Wf[(k + 3) * 32 + lane], fd);
                    }
                    float f = sigm(fd + bfh + fxn);
                    fc = fmaf(f, __ldcg(g_c + ch * 256 + col), fc);
                    __syncwarp();
                }

                if (cs1 > cs0) {
#pragma unroll
                    for (int q = 0; q < 8; q++) hs[q * 32 + lane] = rs[q];
                    __syncwarp();
#pragma unroll 4
                    for (int k = 0; k < 256; k += 4) {
                        float4 h4 = *(const float4*)(hs + k);
                        id = fmaf(h4.x, Wi[(k + 0) * 32 + lane], id);
                        id = fmaf(h4.y, Wi[(k + 1) * 32 + lane], id);
                        id = fmaf(h4.z, Wi[(k + 2) * 32 + lane], id);
                        id = fmaf(h4.w, Wi[(k + 3) * 32 + lane], id);
                        od = fmaf(h4.x, Wo[(k + 0) * 32 + lane], od);
                        od = fmaf(h4.y, Wo[(k + 1) * 32 + lane], od);
                        od = fmaf(h4.z, Wo[(k + 2) * 32 + lane], od);
                        od = fmaf(h4.w, Wo[(k + 3) * 32 + lane], od);
                        ud = fmaf(h4.x, Wu[(k + 0) * 32 + lane], ud);
                        ud = fmaf(h4.y, Wu[(k + 1) * 32 + lane], ud);
                        ud = fmaf(h4.z, Wu[(k + 2) * 32 + lane], ud);
                        ud = fmaf(h4.w, Wu[(k + 3) * 32 + lane], ud);
                    }
                }
                float iv = sigm(g_ix[n * 256 + col] + id + bih);
                float ov = sigm(g_ox[n * 256 + col] + od);
                float uv = tanhf(g_ux[n * 256 + col] + ud);
                float cn = fmaf(iv, uv, fc);
                g_c[n * 256 + col] = cn;
                g_h[n * 256 + col] = ov * tanhf(cn);
            }
        }
        // ---- software grid barrier across 144 co-resident CTAs ----
        __threadfence();
        __syncthreads();
        if (t == 0) {
            unsigned gen = *((volatile unsigned*)&g_bar_gen);
            unsigned a = atomicAdd(&g_bar_count, 1u);
            if (a == NCTA - 1) {
                g_bar_count = 0;
                __threadfence();
                atomicAdd(&g_bar_gen, 1u);
            } else {
                while (*((volatile unsigned*)&g_bar_gen) == gen) {}
            }
        }
        __syncthreads();
    }
}

// ---------------- max-pool over S + output projection -----------------------
__global__ void __launch_bounds__(256) pool_out_kernel(
    const float* __restrict__ Wout, const float* __restrict__ bout,
    float* __restrict__ out)
{
    __shared__ float pooled[Hh];
    int b = blockIdx.x, t = threadIdx.x;
    const float* hb = g_h + b * St * Hh;
    float m = -1e30f;
    for (int s2 = 0; s2 < St; s2++) m = fmaxf(m, hb[s2 * Hh + t]);
    pooled[t] = m;
    __syncthreads();
    if (t < Lc) {
        float acc = bout[t];
        for (int k = 0; k < Hh; k++) acc = fmaf(pooled[k], Wout[k * Lc + t], acc);
        out[b * Lc + t] = acc;
    }
}

// ---------------- host-side launch ------------------------------------------
extern "C" void kernel_launch(void* const* d_in, const int* in_sizes, int n_in,
                              void* d_out, int out_size)
{
    // n_levels (python int) may or may not be forwarded as a size-1 array
    int off = (in_sizes[5] == 1) ? 6 : 5;

    const int* xs        = (const int*)d_in[0];
    const int* rels      = (const int*)d_in[1];
    const int* child_idx = (const int*)d_in[2];
    const int* parent_idx= (const int*)d_in[3];
    const int* height    = (const int*)d_in[4];
    const float* embW  = (const float*)d_in[off + 0];
    const float* relW  = (const float*)d_in[off + 1];
    const float* W_ix  = (const float*)d_in[off + 2];
    const float* b_ix  = (const float*)d_in[off + 3];
    const float* W_ih  = (const float*)d_in[off + 4];
    const float* b_ih  = (const float*)d_in[off + 5];
    const float* W_fx  = (const float*)d_in[off + 6];
    const float* b_fx  = (const float*)d_in[off + 7];
    const float* W_fh  = (const float*)d_in[off + 8];
    const float* b_fh  = (const float*)d_in[off + 9];
    const float* W_ox  = (const float*)d_in[off + 10];
    const float* W_oh  = (const float*)d_in[off + 11];
    const float* W_ux  = (const float*)d_in[off + 12];
    const float* W_uh  = (const float*)d_in[off + 13];
    const float* W_out = (const float*)d_in[off + 14];
    const float* b_out = (const float*)d_in[off + 15];

    cudaFuncSetAttribute(rec_kernel,
                         cudaFuncAttributeMaxDynamicSharedMemorySize, 147456);

    preprocess_kernel<<<1, 256>>>(child_idx, parent_idx, height);
    embed_kernel<<<512, 256>>>(xs, rels, embW, relW);
    dim3 gg(4, 32, 4);
    input_gemm_kernel<<<gg, 256>>>(W_ix, W_fx, W_ox, W_ux, b_ix, b_fx);
    rec_kernel<<<NCTA, 256, 147456>>>(W_ih, W_oh, W_uh, W_fh, b_ih, b_fh);
    pool_out_kernel<<<Bt, 256>>>(W_out, b_out, (float*)d_out);
}

// round 3
// speedup vs baseline: 1.2629x; 1.2629x over previous
#include <cuda_runtime.h>
#include <math.h>

#define Bt    16
#define St    128
#define Nn    2048
#define Ee    2032
#define Hh    256
#define DINc  256
#define DEc   192
#define DRc   64
#define Lc    12
#define NLEVc 21
#define NGRP  18
#define NCTA  144
#define NW    16
#define WPC   (NGRP * NW)   // 288 warps per column-block

typedef unsigned long long u64;

// ---------------- device scratch (no dynamic allocation allowed) ------------
__device__ float g_x [Nn * DINc];
__device__ float g_ix[Nn * Hh];
__device__ float g_fx[Nn * Hh];
__device__ float g_ox[Nn * Hh];
__device__ float g_ux[Nn * Hh];
__device__ float g_h [Nn * Hh];
__device__ float g_c [Nn * Hh];
__device__ int   g_child_start[Nn + 1];
__device__ int   g_child_list [Ee];
__device__ int   g_level_start[NLEVc + 1];
__device__ int   g_level_nodes[Nn];
__device__ int   g_done[Nn];

// ---------------- f32x2 helpers ---------------------------------------------
__device__ __forceinline__ u64 pk2(float a, float b) {
    u64 r; asm("mov.b64 %0,{%1,%2};" : "=l"(r) : "f"(a), "f"(b)); return r;
}
__device__ __forceinline__ void fma2(u64& d, u64 a, u64 b) {
    asm("fma.rn.f32x2 %0,%1,%2,%0;" : "+l"(d) : "l"(a), "l"(b));
}
__device__ __forceinline__ float red2(u64 v) {
    float a, b; asm("mov.b64 {%0,%1},%2;" : "=f"(a), "=f"(b) : "l"(v));
    return a + b;
}
__device__ __forceinline__ float sigm(float x) { return 1.f / (1.f + __expf(-x)); }

// ---------------- preprocess: child CSR + level lists (single block) --------
__global__ void __launch_bounds__(256) preprocess_kernel(
    const int* __restrict__ child_idx,
    const int* __restrict__ parent_idx,
    const int* __restrict__ node_height)
{
    __shared__ int s_cnt[Nn];
    __shared__ int s_aux[256];
    __shared__ int s_lvl[NLEVc + 1];
    const int t = threadIdx.x;

    for (int i = t; i < Nn; i += 256) { s_cnt[i] = 0; g_done[i] = 0; }
    if (t <= NLEVc) s_lvl[t] = 0;
    __syncthreads();

    for (int e = t; e < Ee; e += 256) atomicAdd(&s_cnt[parent_idx[e]], 1);
    for (int i = t; i < Nn; i += 256) atomicAdd(&s_lvl[node_height[i]], 1);
    __syncthreads();

    int v[8]; int s = 0;
#pragma unroll
    for (int r = 0; r < 8; r++) { v[r] = s_cnt[t * 8 + r]; s += v[r]; }
    s_aux[t] = s;
    __syncthreads();
    for (int off = 1; off < 256; off <<= 1) {
        int x = (t >= off) ? s_aux[t - off] : 0;
        __syncthreads();
        s_aux[t] += x;
        __syncthreads();
    }
    int run = (t == 0) ? 0 : s_aux[t - 1];
#pragma unroll
    for (int r = 0; r < 8; r++) {
        int c = v[r];
        g_child_start[t * 8 + r] = run;
        s_cnt[t * 8 + r] = run;
        run += c;
    }
    if (t == 255) g_child_start[Nn] = run;
    __syncthreads();

    if (t == 0) {
        int acc = 0;
        for (int l = 0; l < NLEVc; l++) {
            int c = s_lvl[l];
            g_level_start[l] = acc;
            s_lvl[l] = acc;
            acc += c;
        }
        g_level_start[NLEVc] = acc;
    }
    __syncthreads();

    if (t < Bt) {
        for (int e = t * (St - 1); e < (t + 1) * (St - 1); e++) {
            int p = parent_idx[e];
            g_child_list[s_cnt[p]++] = child_idx[e];
        }
    }
    for (int i = t; i < Nn; i += 256) {
        int pos = atomicAdd(&s_lvl[node_height[i]], 1);
        g_level_nodes[pos] = i;
    }
}

// ---------------- embedding gather ------------------------------------------
__global__ void __launch_bounds__(256) embed_kernel(
    const int* __restrict__ xs, const int* __restrict__ rels,
    const float* __restrict__ embW, const float* __restrict__ relW)
{
    int i = blockIdx.x * blockDim.x + threadIdx.x;
    int idx = i * 4;
    if (idx >= Nn * DINc) return;
    int n = idx >> 8;
    int d = idx & 255;
    float4 vv;
    if (d < DEc) vv = *(const float4*)(embW + (size_t)xs[n] * DEc + d);
    else         vv = *(const float4*)(relW + (size_t)rels[n] * DRc + (d - DEc));
    *(float4*)(g_x + idx) = vv;
}

// ---------------- fused input GEMMs: g_x[2048,256] @ W[256,256] (x4) --------
__global__ void __launch_bounds__(256) input_gemm_kernel(
    const float* __restrict__ Wix, const float* __restrict__ Wfx,
    const float* __restrict__ Wox, const float* __restrict__ Wux,
    const float* __restrict__ bix, const float* __restrict__ bfx)
{
    __shared__ __align__(16) float As[16][68];
    __shared__ __align__(16) float Bs[16][68];
    const int mz = blockIdx.z;
    const float* W  = (mz == 0) ? Wix : (mz == 1) ? Wfx : (mz == 2) ? Wox : Wux;
    const float* bp = (mz == 0) ? bix : (mz == 1) ? bfx : nullptr;
    float* O = (mz == 0) ? g_ix : (mz == 1) ? g_fx : (mz == 2) ? g_ox : g_ux;

    const int t = threadIdx.x;
    const int tx = t & 15, ty = t >> 4;
    const int row0 = blockIdx.y * 64, col0 = blockIdx.x * 64;
    float acc[4][4] = {};

    for (int kk = 0; kk < 256; kk += 16) {
        {
            int m = t >> 2, kq = (t & 3) * 4;
            float4 a = *(const float4*)(g_x + (row0 + m) * 256 + kk + kq);
            As[kq + 0][m] = a.x; As[kq + 1][m] = a.y;
            As[kq + 2][m] = a.z; As[kq + 3][m] = a.w;
            int k = t >> 4, nq = (t & 15) * 4;
            float4 b = *(const float4*)(W + (kk + k) * 256 + col0 + nq);
            *(float4*)&Bs[k][nq] = b;
        }
        __syncthreads();
#pragma unroll
        for (int k = 0; k < 16; k++) {
            float4 a = *(const float4*)&As[k][ty * 4];
            float4 b = *(const float4*)&Bs[k][tx * 4];
            acc[0][0] = fmaf(a.x, b.x, acc[0][0]); acc[0][1] = fmaf(a.x, b.y, acc[0][1]);
            acc[0][2] = fmaf(a.x, b.z, acc[0][2]); acc[0][3] = fmaf(a.x, b.w, acc[0][3]);
            acc[1][0] = fmaf(a.y, b.x, acc[1][0]); acc[1][1] = fmaf(a.y, b.y, acc[1][1]);
            acc[1][2] = fmaf(a.y, b.z, acc[1][2]); acc[1][3] = fmaf(a.y, b.w, acc[1][3]);
            acc[2][0] = fmaf(a.z, b.x, acc[2][0]); acc[2][1] = fmaf(a.z, b.y, acc[2][1]);
            acc[2][2] = fmaf(a.z, b.z, acc[2][2]); acc[2][3] = fmaf(a.z, b.w, acc[2][3]);
            acc[3][0] = fmaf(a.w, b.x, acc[3][0]); acc[3][1] = fmaf(a.w, b.y, acc[3][1]);
            acc[3][2] = fmaf(a.w, b.z, acc[3][2]); acc[3][3] = fmaf(a.w, b.w, acc[3][3]);
        }
        __syncthreads();
    }
    int cc0 = col0 + tx * 4;
    float4 bb = make_float4(0.f, 0.f, 0.f, 0.f);
    if (bp) bb = *(const float4*)(bp + cc0);
#pragma unroll
    for (int i2 = 0; i2 < 4; i2++) {
        int r = row0 + ty * 4 + i2;
        float4 o;
        o.x = acc[i2][0] + bb.x; o.y = acc[i2][1] + bb.y;
        o.z = acc[i2][2] + bb.z; o.w = acc[i2][3] + bb.w;
        *(float4*)(O + r * 256 + cc0) = o;
    }
}

// ---------------- dataflow recurrence: per-node done flags, no barriers -----
// CTA = (column-block cb of 32 H-cols, group g). 288 warps per cb process the
// level-ordered node list round-robin; waits always target strictly smaller
// list positions -> deadlock-free.
__global__ void __launch_bounds__(512) rec_kernel(
    const float* __restrict__ Wih, const float* __restrict__ Woh,
    const float* __restrict__ Wuh, const float* __restrict__ Wfh,
    const float* __restrict__ bih_g, const float* __restrict__ bfh_g)
{
    extern __shared__ __align__(16) float sm[];
    float* Wi = sm;              // each 8192 floats, pair-interleaved:
    float* Wo = sm + 8192;       //   W*[k2*64 + lane*2 + s] = W[2*k2+s][cb*32+lane]
    float* Wu = sm + 16384;
    float* Wf = sm + 24576;
    float* hchAll = sm + 32768;  // 16 warps x 256

    const int t = threadIdx.x;
    const int lane = t & 31, w = t >> 5;
    const int cb = blockIdx.x & 7;
    const int g  = blockIdx.x >> 3;
    const int col = cb * 32 + lane;
    const int ws = g * NW + w;

    for (int p = t; p < 4096; p += 512) {
        int k2 = p >> 5, j = p & 31;
        int g0 = (2 * k2) * 256 + cb * 32 + j;
        int o = k2 * 64 + j * 2;
        Wi[o] = Wih[g0]; Wi[o + 1] = Wih[g0 + 256];
        Wo[o] = Woh[g0]; Wo[o + 1] = Woh[g0 + 256];
        Wu[o] = Wuh[g0]; Wu[o + 1] = Wuh[g0 + 256];
        Wf[o] = Wfh[g0]; Wf[o + 1] = Wfh[g0 + 256];
    }
    const float bih = bih_g[col];
    const float bfh = bfh_g[col];
    float* hch = hchAll + w * 256;
    const u64* Wi2 = (const u64*)Wi;
    const u64* Wo2 = (const u64*)Wo;
    const u64* Wu2 = (const u64*)Wu;
    const u64* Wf2 = (const u64*)Wf;
    __syncthreads();

    for (int pos = ws; pos < Nn; pos += WPC) {
        int n = g_level_nodes[pos];
        int cs0 = g_child_start[n], cs1 = g_child_start[n + 1];
        float ov, cn;
        if (cs1 == cs0) {                         // leaf: h_sum = 0, fc = 0
            float iv = sigm(g_ix[n * 256 + col] + bih);
            ov = sigm(g_ox[n * 256 + col]);
            float uv = tanhf(g_ux[n * 256 + col]);
            cn = iv * uv;
        } else {
            float fxn = g_fx[n * 256 + col];
            float rs[8];
#pragma unroll
            for (int q = 0; q < 8; q++) rs[q] = 0.f;
            float fc = 0.f;

            for (int e = cs0; e < cs1; e++) {
                int ch = g_child_list[e];
                if (lane == 0) {
                    while (*((volatile int*)&g_done[ch]) != 8) __nanosleep(32);
                }
                __syncwarp();
                __threadfence();
                const float* hrow = g_h + ch * 256;
#pragma unroll
                for (int q = 0; q < 8; q++) {
                    float vv = __ldcg(hrow + q * 32 + lane);
                    hch[q * 32 + lane] = vv;
                    rs[q] += vv;
                }
                float cch = __ldcg(g_c + ch * 256 + col);
                __syncwarp();
                u64 a0 = 0, a1 = 0, a2 = 0, a3 = 0;
#pragma unroll 8
                for (int k2 = 0; k2 < 128; k2 += 4) {
                    float4 hA = *(const float4*)(hch + 2 * k2);
                    float4 hB = *(const float4*)(hch + 2 * k2 + 4);
                    fma2(a0, pk2(hA.x, hA.y), Wf2[(k2 + 0) * 32 + lane]);
                    fma2(a1, pk2(hA.z, hA.w), Wf2[(k2 + 1) * 32 + lane]);
                    fma2(a2, pk2(hB.x, hB.y), Wf2[(k2 + 2) * 32 + lane]);
                    fma2(a3, pk2(hB.z, hB.w), Wf2[(k2 + 3) * 32 + lane]);
                }
                float fd = red2(a0) + red2(a1) + red2(a2) + red2(a3);
                float f = sigm(fd + bfh + fxn);
                fc = fmaf(f, cch, fc);
                __syncwarp();
            }

            // h_sum -> smem (broadcast source for i/o/u dots)
#pragma unroll
            for (int q = 0; q < 8; q++) hch[q * 32 + lane] = rs[q];
            __syncwarp();
            u64 i0 = 0, i1 = 0, o0 = 0, o1 = 0, u0 = 0, u1 = 0;
#pragma unroll 4
            for (int k2 = 0; k2 < 128; k2 += 2) {
                float4 h4 = *(const float4*)(hch + 2 * k2);
                u64 p01 = pk2(h4.x, h4.y), p23 = pk2(h4.z, h4.w);
                fma2(i0, p01, Wi2[(k2 + 0) * 32 + lane]);
                fma2(i1, p23, Wi2[(k2 + 1) * 32 + lane]);
                fma2(o0, p01, Wo2[(k2 + 0) * 32 + lane]);
                fma2(o1, p23, Wo2[(k2 + 1) * 32 + lane]);
                fma2(u0, p01, Wu2[(k2 + 0) * 32 + lane]);
                fma2(u1, p23, Wu2[(k2 + 1) * 32 + lane]);
            }
            float iv = sigm(g_ix[n * 256 + col] + red2(i0) + red2(i1) + bih);
            ov = sigm(g_ox[n * 256 + col] + red2(o0) + red2(o1));
            float uv = tanhf(g_ux[n * 256 + col] + red2(u0) + red2(u1));
            cn = fmaf(iv, uv, fc);
            __syncwarp();
        }
        __stcg(g_c + n * 256 + col, cn);
        __stcg(g_h + n * 256 + col, ov * tanhf(cn));
        __threadfence();
        if (lane == 0) atomicAdd(&g_done[n], 1);
    }
}

// ---------------- max-pool over S + output projection -----------------------
__global__ void __launch_bounds__(256) pool_out_kernel(
    const float* __restrict__ Wout, const float* __restrict__ bout,
    float* __restrict__ out)
{
    __shared__ float pooled[Hh];
    int b = blockIdx.x, t = threadIdx.x;
    const float* hb = g_h + b * St * Hh;
    float m = -1e30f;
    for (int s2 = 0; s2 < St; s2++) m = fmaxf(m, hb[s2 * Hh + t]);
    pooled[t] = m;
    __syncthreads();
    if (t < Lc) {
        float acc = bout[t];
        for (int k = 0; k < Hh; k++) acc = fmaf(pooled[k], Wout[k * Lc + t], acc);
        out[b * Lc + t] = acc;
    }
}

// ---------------- host-side launch ------------------------------------------
extern "C" void kernel_launch(void* const* d_in, const int* in_sizes, int n_in,
                              void* d_out, int out_size)
{
    int off = (in_sizes[5] == 1) ? 6 : 5;

    const int* xs        = (const int*)d_in[0];
    const int* rels      = (const int*)d_in[1];
    const int* child_idx = (const int*)d_in[2];
    const int* parent_idx= (const int*)d_in[3];
    const int* height    = (const int*)d_in[4];
    const float* embW  = (const float*)d_in[off + 0];
    const float* relW  = (const float*)d_in[off + 1];
    const float* W_ix  = (const float*)d_in[off + 2];
    const float* b_ix  = (const float*)d_in[off + 3];
    const float* W_ih  = (const float*)d_in[off + 4];
    const float* b_ih  = (const float*)d_in[off + 5];
    const float* W_fx  = (const float*)d_in[off + 6];
    const float* b_fx  = (const float*)d_in[off + 7];
    const float* W_fh  = (const float*)d_in[off + 8];
    const float* b_fh  = (const float*)d_in[off + 9];
    const float* W_ox  = (const float*)d_in[off + 10];
    const float* W_oh  = (const float*)d_in[off + 11];
    const float* W_ux  = (const float*)d_in[off + 12];
    const float* W_uh  = (const float*)d_in[off + 13];
    const float* W_out = (const float*)d_in[off + 14];
    const float* b_out = (const float*)d_in[off + 15];

    cudaFuncSetAttribute(rec_kernel,
                         cudaFuncAttributeMaxDynamicSharedMemorySize, 163840);

    preprocess_kernel<<<1, 256>>>(child_idx, parent_idx, height);
    embed_kernel<<<512, 256>>>(xs, rels, embW, relW);
    dim3 gg(4, 32, 4);
    input_gemm_kernel<<<gg, 256>>>(W_ix, W_fx, W_ox, W_ux, b_ix, b_fx);
    rec_kernel<<<NCTA, 512, 163840>>>(W_ih, W_oh, W_uh, W_fh, b_ih, b_fh);
    pool_out_kernel<<<Bt, 256>>>(W_out, b_out, (float*)d_out);
}

// round 4
// speedup vs baseline: 1.8703x; 1.4809x over previous
#include <cuda_runtime.h>
#include <math.h>

#define Bt    16
#define St    128
#define Nn    2048
#define Ee    2032
#define Hh    256
#define DINc  256
#define DEc   192
#define DRc   64
#define Lc    12
#define NLEVc 21
#define NGRP  18
#define NCTA  144
#define NW    16

typedef unsigned long long u64;

// ---------------- device scratch (no dynamic allocation allowed) ------------
__device__ float g_ix[Nn * Hh];
__device__ float g_fx[Nn * Hh];
__device__ float g_ox[Nn * Hh];
__device__ float g_ux[Nn * Hh];
__device__ float g_h [Nn * Hh];
__device__ float g_c [Nn * Hh];
__device__ int   g_child_start[Nn + 1];
__device__ int   g_child_list [Ee];
__device__ int   g_level_nodes[Nn];
__device__ int   g_done[Nn];
__device__ int   g_cursor[8 * 32];   // one cursor per column-block, padded

// ---------------- helpers ----------------------------------------------------
__device__ __forceinline__ u64 pk2(float a, float b) {
    u64 r; asm("mov.b64 %0,{%1,%2};" : "=l"(r) : "f"(a), "f"(b)); return r;
}
__device__ __forceinline__ u64 dup2(float a) {
    u64 r; asm("mov.b64 %0,{%1,%1};" : "=l"(r) : "f"(a)); return r;
}
__device__ __forceinline__ void fma2(u64& d, u64 a, u64 b) {
    asm("fma.rn.f32x2 %0,%1,%2,%0;" : "+l"(d) : "l"(a), "l"(b));
}
__device__ __forceinline__ float red2(u64 v) {
    float a, b; asm("mov.b64 {%0,%1},%2;" : "=f"(a), "=f"(b) : "l"(v));
    return a + b;
}
__device__ __forceinline__ float lo2(u64 v) {
    float a, b; asm("mov.b64 {%0,%1},%2;" : "=f"(a), "=f"(b) : "l"(v)); return a;
}
__device__ __forceinline__ float hi2(u64 v) {
    float a, b; asm("mov.b64 {%0,%1},%2;" : "=f"(a), "=f"(b) : "l"(v)); return b;
}
__device__ __forceinline__ int ldacq(const int* p) {
    int v; asm volatile("ld.acquire.gpu.global.s32 %0,[%1];" : "=r"(v) : "l"(p) : "memory");
    return v;
}
__device__ __forceinline__ void red_release(int* p) {
    asm volatile("red.release.gpu.global.add.s32 [%0],1;" :: "l"(p) : "memory");
}
__device__ __forceinline__ float sigm(float x) { return 1.f / (1.f + __expf(-x)); }

// ---------------- preprocess: child CSR + level lists (single block) --------
__global__ void __launch_bounds__(512) preprocess_kernel(
    const int* __restrict__ child_idx,
    const int* __restrict__ parent_idx,
    const int* __restrict__ node_height)
{
    __shared__ int s_cnt[Nn];
    __shared__ int s_aux[512];
    __shared__ int s_par[Ee];
    __shared__ int s_lvl[NLEVc + 1];
    const int t = threadIdx.x;

    for (int i = t; i < Nn; i += 512) { s_cnt[i] = 0; g_done[i] = 0; }
    for (int e = t; e < Ee; e += 512) s_par[e] = parent_idx[e];
    if (t <= NLEVc) s_lvl[t] = 0;
    if (t < 8) g_cursor[t * 32] = 0;
    __syncthreads();

    for (int e = t; e < Ee; e += 512) atomicAdd(&s_cnt[s_par[e]], 1);
    for (int i = t; i < Nn; i += 512) atomicAdd(&s_lvl[node_height[i]], 1);
    __syncthreads();

    // exclusive scan of 2048 child counts: 4 per thread + 512-wide scan
    int v[4]; int s = 0;
#pragma unroll
    for (int r = 0; r < 4; r++) { v[r] = s_cnt[t * 4 + r]; s += v[r]; }
    s_aux[t] = s;
    __syncthreads();
    for (int off = 1; off < 512; off <<= 1) {
        int x = (t >= off) ? s_aux[t - off] : 0;
        __syncthreads();
        s_aux[t] += x;
        __syncthreads();
    }
    int run = (t == 0) ? 0 : s_aux[t - 1];
#pragma unroll
    for (int r = 0; r < 4; r++) {
        int c = v[r];
        g_child_start[t * 4 + r] = run;
        s_cnt[t * 4 + r] = run;
        run += c;
    }
    if (t == 511) g_child_start[Nn] = run;
    __syncthreads();

    if (t == 0) {
        int acc = 0;
        for (int l = 0; l < NLEVc; l++) {
            int c = s_lvl[l];
            s_lvl[l] = acc;
            acc += c;
        }
    }
    __syncthreads();

    // warp-per-tree child scatter: rank = #earlier same-parent edges in tree
    {
        int w = t >> 5, lane = t & 31;
        if (w < Bt) {
            int e0 = w * (St - 1);
            for (int el = lane; el < St - 1; el += 32) {
                int e = e0 + el;
                int p = s_par[e];
                int rank = 0;
                for (int e2 = e0; e2 < e; ++e2) rank += (s_par[e2] == p) ? 1 : 0;
                g_child_list[s_cnt[p] + rank] = child_idx[e];
            }
        }
    }
    // level-node scatter (intra-level order irrelevant)
    for (int i = t; i < Nn; i += 512) {
        int pos = atomicAdd(&s_lvl[node_height[i]], 1);
        g_level_nodes[pos] = i;
    }
}

// ---------------- fused embed + input GEMMs: x[2048,256] @ W[256,256] (x4) --
__global__ void __launch_bounds__(256) input_gemm_kernel(
    const int* __restrict__ xs, const int* __restrict__ rels,
    const float* __restrict__ embW, const float* __restrict__ relW,
    const float* __restrict__ Wix, const float* __restrict__ Wfx,
    const float* __restrict__ Wox, const float* __restrict__ Wux,
    const float* __restrict__ bix, const float* __restrict__ bfx)
{
    __shared__ __align__(16) float As[16][68];
    __shared__ __align__(16) float Bs[16][68];
    __shared__ int s_xs[64], s_rels[64];
    const int mz = blockIdx.z;
    const float* W  = (mz == 0) ? Wix : (mz == 1) ? Wfx : (mz == 2) ? Wox : Wux;
    const float* bp = (mz == 0) ? bix : (mz == 1) ? bfx : nullptr;
    float* O = (mz == 0) ? g_ix : (mz == 1) ? g_fx : (mz == 2) ? g_ox : g_ux;

    const int t = threadIdx.x;
    const int tx = t & 15, ty = t >> 4;
    const int row0 = blockIdx.y * 64, col0 = blockIdx.x * 64;
    if (t < 64) { s_xs[t] = xs[row0 + t]; s_rels[t] = rels[row0 + t]; }
    __syncthreads();

    u64 acc[4][2] = {};

    for (int kk = 0; kk < 256; kk += 16) {
        {
            int m = t >> 2, kq = (t & 3) * 4;
            int gk = kk + kq;
            float4 a;
            if (gk < DEc) a = *(const float4*)(embW + (size_t)s_xs[m] * DEc + gk);
            else          a = *(const float4*)(relW + (size_t)s_rels[m] * DRc + (gk - DEc));
            As[kq + 0][m] = a.x; As[kq + 1][m] = a.y;
            As[kq + 2][m] = a.z; As[kq + 3][m] = a.w;
            int k = t >> 4, nq = (t & 15) * 4;
            float4 b = *(const float4*)(W + (kk + k) * 256 + col0 + nq);
            *(float4*)&Bs[k][nq] = b;
        }
        __syncthreads();
#pragma unroll
        for (int k = 0; k < 16; k++) {
            float4 a = *(const float4*)&As[k][ty * 4];
            u64 b0 = *(const u64*)&Bs[k][tx * 4];
            u64 b1 = *(const u64*)&Bs[k][tx * 4 + 2];
            u64 d;
            d = dup2(a.x); fma2(acc[0][0], d, b0); fma2(acc[0][1], d, b1);
            d = dup2(a.y); fma2(acc[1][0], d, b0); fma2(acc[1][1], d, b1);
            d = dup2(a.z); fma2(acc[2][0], d, b0); fma2(acc[2][1], d, b1);
            d = dup2(a.w); fma2(acc[3][0], d, b0); fma2(acc[3][1], d, b1);
        }
        __syncthreads();
    }
    int cc0 = col0 + tx * 4;
    float4 bb = make_float4(0.f, 0.f, 0.f, 0.f);
    if (bp) bb = *(const float4*)(bp + cc0);
#pragma unroll
    for (int r = 0; r < 4; r++) {
        int row = row0 + ty * 4 + r;
        float4 o;
        o.x = lo2(acc[r][0]) + bb.x; o.y = hi2(acc[r][0]) + bb.y;
        o.z = lo2(acc[r][1]) + bb.z; o.w = hi2(acc[r][1]) + bb.w;
        *(float4*)(O + row * 256 + cc0) = o;
    }
}

// ---------------- dataflow recurrence: dynamic schedule + acquire/release ---
__global__ void __launch_bounds__(512) rec_kernel(
    const float* __restrict__ Wih, const float* __restrict__ Woh,
    const float* __restrict__ Wuh, const float* __restrict__ Wfh,
    const float* __restrict__ bih_g, const float* __restrict__ bfh_g)
{
    extern __shared__ __align__(16) float sm[];
    float* Wi = sm;              // each 8192 floats, pair-interleaved:
    float* Wo = sm + 8192;       //   W*[k2*64 + lane*2 + s] = W[2*k2+s][cb*32+lane]
    float* Wu = sm + 16384;
    float* Wf = sm + 24576;
    float* hchAll = sm + 32768;  // 16 warps x 256

    const int t = threadIdx.x;
    const int lane = t & 31, w = t >> 5;
    const int cb = blockIdx.x & 7;
    const int col = cb * 32 + lane;

    for (int p = t; p < 4096; p += 512) {
        int k2 = p >> 5, j = p & 31;
        int g0 = (2 * k2) * 256 + cb * 32 + j;
        int o = k2 * 64 + j * 2;
        Wi[o] = Wih[g0]; Wi[o + 1] = Wih[g0 + 256];
        Wo[o] = Woh[g0]; Wo[o + 1] = Woh[g0 + 256];
        Wu[o] = Wuh[g0]; Wu[o + 1] = Wuh[g0 + 256];
        Wf[o] = Wfh[g0]; Wf[o + 1] = Wfh[g0 + 256];
    }
    const float bih = bih_g[col];
    const float bfh = bfh_g[col];
    float* hch = hchAll + w * 256;
    const u64* Wi2 = (const u64*)Wi;
    const u64* Wo2 = (const u64*)Wo;
    const u64* Wu2 = (const u64*)Wu;
    const u64* Wf2 = (const u64*)Wf;
    __syncthreads();

    for (;;) {
        int pos;
        if (lane == 0) pos = atomicAdd(&g_cursor[cb * 32], 1);
        pos = __shfl_sync(0xffffffffu, pos, 0);
        if (pos >= Nn) break;
        int n = g_level_nodes[pos];
        int cs0 = g_child_start[n], cs1 = g_child_start[n + 1];
        float ixv = g_ix[n * 256 + col];
        float oxv = g_ox[n * 256 + col];
        float uxv = g_ux[n * 256 + col];
        float ov, cn;
        if (cs1 == cs0) {                          // leaf: h_sum = 0, fc = 0
            float iv = sigm(ixv + bih);
            ov = sigm(oxv);
            cn = iv * tanhf(uxv);
        } else {
            float fxn = g_fx[n * 256 + col];
            float rs[8];
#pragma unroll
            for (int q = 0; q < 8; q++) rs[q] = 0.f;
            float fc = 0.f;

            for (int e = cs0; e < cs1; e++) {
                int ch = g_child_list[e];
                {
                    int it = 0;
                    while (ldacq(&g_done[ch]) != 8) {
                        if (++it > 48) __nanosleep(256);
                    }
                }
                const float* hrow = g_h + ch * 256;
#pragma unroll
                for (int q = 0; q < 8; q++) {
                    float vv = __ldcg(hrow + q * 32 + lane);
                    hch[q * 32 + lane] = vv;
                    rs[q] += vv;
                }
                float cch = __ldcg(g_c + ch * 256 + col);
                __syncwarp();
                u64 a0 = 0, a1 = 0, a2 = 0, a3 = 0;
#pragma unroll 8
                for (int k2 = 0; k2 < 128; k2 += 4) {
                    float4 hA = *(const float4*)(hch + 2 * k2);
                    float4 hB = *(const float4*)(hch + 2 * k2 + 4);
                    fma2(a0, pk2(hA.x, hA.y), Wf2[(k2 + 0) * 32 + lane]);
                    fma2(a1, pk2(hA.z, hA.w), Wf2[(k2 + 1) * 32 + lane]);
                    fma2(a2, pk2(hB.x, hB.y), Wf2[(k2 + 2) * 32 + lane]);
                    fma2(a3, pk2(hB.z, hB.w), Wf2[(k2 + 3) * 32 + lane]);
                }
                float fd = red2(a0) + red2(a1) + red2(a2) + red2(a3);
                float f = sigm(fd + bfh + fxn);
                fc = fmaf(f, cch, fc);
                __syncwarp();
            }

            // h_sum -> smem (broadcast source for i/o/u dots)
#pragma unroll
            for (int q = 0; q < 8; q++) hch[q * 32 + lane] = rs[q];
            __syncwarp();
            u64 i0 = 0, i1 = 0, o0 = 0, o1 = 0, u0 = 0, u1 = 0;
#pragma unroll 4
            for (int k2 = 0; k2 < 128; k2 += 2) {
                float4 h4 = *(const float4*)(hch + 2 * k2);
                u64 p01 = pk2(h4.x, h4.y), p23 = pk2(h4.z, h4.w);
                fma2(i0, p01, Wi2[(k2 + 0) * 32 + lane]);
                fma2(i1, p23, Wi2[(k2 + 1) * 32 + lane]);
                fma2(o0, p01, Wo2[(k2 + 0) * 32 + lane]);
                fma2(o1, p23, Wo2[(k2 + 1) * 32 + lane]);
                fma2(u0, p01, Wu2[(k2 + 0) * 32 + lane]);
                fma2(u1, p23, Wu2[(k2 + 1) * 32 + lane]);
            }
            float iv = sigm(ixv + red2(i0) + red2(i1) + bih);
            ov = sigm(oxv + red2(o0) + red2(o1));
            float uv = tanhf(uxv + red2(u0) + red2(u1));
            cn = fmaf(iv, uv, fc);
            __syncwarp();
        }
        __stcg(g_c + n * 256 + col, cn);
        __stcg(g_h + n * 256 + col, ov * tanhf(cn));
        __syncwarp();
        if (lane == 0) red_release(&g_done[n]);
    }
}

// ---------------- max-pool over S + output projection -----------------------
__global__ void __launch_bounds__(256) pool_out_kernel(
    const float* __restrict__ Wout, const float* __restrict__ bout,
    float* __restrict__ out)
{
    __shared__ float pooled[Hh];
    int b = blockIdx.x, t = threadIdx.x;
    const float* hb = g_h + b * St * Hh;
    float m = -1e30f;
    for (int s2 = 0; s2 < St; s2++) m = fmaxf(m, hb[s2 * Hh + t]);
    pooled[t] = m;
    __syncthreads();
    if (t < Lc) {
        float acc = bout[t];
        for (int k = 0; k < Hh; k++) acc = fmaf(pooled[k], Wout[k * Lc + t], acc);
        out[b * Lc + t] = acc;
    }
}

// ---------------- host-side launch ------------------------------------------
extern "C" void kernel_launch(void* const* d_in, const int* in_sizes, int n_in,
                              void* d_out, int out_size)
{
    int off = (in_sizes[5] == 1) ? 6 : 5;

    const int* xs        = (const int*)d_in[0];
    const int* rels      = (const int*)d_in[1];
    const int* child_idx = (const int*)d_in[2];
    const int* parent_idx= (const int*)d_in[3];
    const int* height    = (const int*)d_in[4];
    const float* embW  = (const float*)d_in[off + 0];
    const float* relW  = (const float*)d_in[off + 1];
    const float* W_ix  = (const float*)d_in[off + 2];
    const float* b_ix  = (const float*)d_in[off + 3];
    const float* W_ih  = (const float*)d_in[off + 4];
    const float* b_ih  = (const float*)d_in[off + 5];
    const float* W_fx  = (const float*)d_in[off + 6];
    const float* b_fx  = (const float*)d_in[off + 7];
    const float* W_fh  = (const float*)d_in[off + 8];
    const float* b_fh  = (const float*)d_in[off + 9];
    const float* W_ox  = (const float*)d_in[off + 10];
    const float* W_oh  = (const float*)d_in[off + 11];
    const float* W_ux  = (const float*)d_in[off + 12];
    const float* W_uh  = (const float*)d_in[off + 13];
    const float* W_out = (const float*)d_in[off + 14];
    const float* b_out = (const float*)d_in[off + 15];

    cudaFuncSetAttribute(rec_kernel,
                         cudaFuncAttributeMaxDynamicSharedMemorySize, 163840);

    preprocess_kernel<<<1, 512>>>(child_idx, parent_idx, height);
    dim3 gg(4, 32, 4);
    input_gemm_kernel<<<gg, 256>>>(xs, rels, embW, relW,
                                   W_ix, W_fx, W_ox, W_ux, b_ix, b_fx);
    rec_kernel<<<NCTA, 512, 163840>>>(W_ih, W_oh, W_uh, W_fh, b_ih, b_fh);
    pool_out_kernel<<<Bt, 256>>>(W_out, b_out, (float*)d_out);
}